// round 14
// baseline (speedup 1.0000x reference)
#include <cuda_runtime.h>
#include <cuda_bf16.h>
#include <cstdint>

// Problem constants
#define DM     256
#define HW     3136
#define NB     2
#define PTOT   (NB*HW)       // 6272 = 49*128 (fused pixel axis)
#define NH     8
#define HD     32
#define WS     7
#define NW     49

// Scratch (device globals). Fused layout: [c][P] with c = h*32+d, P = b*HW+p.
__device__ float g_q[DM * PTOT];
__device__ float g_k[DM * PTOT];
__device__ float g_v[DM * PTOT];
__device__ float g_a[DM * PTOT];

// Partial-score / probability slab: [group][z][y0b][i][at] packed f32x2.
#define SLABSZ (16 * 14 * NW * 112)          // 1,229,312 u64 per group
typedef unsigned long long u64;
__device__ u64 g_sc[2 * SLABSZ];             // ~19.7 MB, L2-resident

// ---- packed f32x2 helpers ---------------------------------------------------
__device__ __forceinline__ u64 pack2s(float v) {
    u64 r; asm("mov.b64 %0, {%1, %1};" : "=l"(r) : "f"(v)); return r;
}
__device__ __forceinline__ u64 packpair(float a, float b) {
    u64 r; asm("mov.b64 %0, {%1, %2};" : "=l"(r) : "f"(a), "f"(b)); return r;
}
__device__ __forceinline__ void ffma2(u64& d, u64 a, u64 b) {
    asm("fma.rn.f32x2 %0, %1, %2, %0;" : "+l"(d) : "l"(a), "l"(b));
}
__device__ __forceinline__ u64 add2(u64 a, u64 b) {
    u64 r; asm("add.rn.f32x2 %0, %1, %2;" : "=l"(r) : "l"(a), "l"(b)); return r;
}
__device__ __forceinline__ u64 mul2(u64 a, u64 b) {
    u64 r; asm("mul.rn.f32x2 %0, %1, %2;" : "=l"(r) : "l"(a), "l"(b)); return r;
}
__device__ __forceinline__ float2 unpack2(u64 v) {
    float2 r; asm("mov.b64 {%0, %1}, %2;" : "=f"(r.x), "=f"(r.y) : "l"(v)); return r;
}

// ---- cp.async helpers -------------------------------------------------------
__device__ __forceinline__ uint32_t smem_u32(const void* p) {
    uint32_t a;
    asm("{ .reg .u64 t; cvta.to.shared.u64 t, %1; cvt.u32.u64 %0, t; }" : "=r"(a) : "l"(p));
    return a;
}
__device__ __forceinline__ void cpa4(uint32_t dst, const float* src, bool ok) {
    asm volatile("cp.async.ca.shared.global [%0], [%1], 4, %2;"
        :: "r"(dst), "l"(src), "r"(ok ? 4u : 0u) : "memory");
}
#define CPA_COMMIT() asm volatile("cp.async.commit_group;" ::: "memory")
#define CPA_WAIT2()  asm volatile("cp.async.wait_group 2;" ::: "memory")

// ---- tf32 mma helpers ------------------------------------------------------
__device__ __forceinline__ uint32_t f2tf32(float v) {
    uint32_t r; asm("cvt.rna.tf32.f32 %0, %1;" : "=r"(r) : "f"(v)); return r;
}
__device__ __forceinline__ void mma_tf32(float* d, const uint32_t* a, const uint32_t* b) {
    asm volatile(
        "mma.sync.aligned.m16n8k8.row.col.f32.tf32.tf32.f32 "
        "{%0,%1,%2,%3}, {%4,%5,%6,%7}, {%8,%9}, {%0,%1,%2,%3};"
        : "+f"(d[0]), "+f"(d[1]), "+f"(d[2]), "+f"(d[3])
        : "r"(a[0]), "r"(a[1]), "r"(a[2]), "r"(a[3]), "r"(b[0]), "r"(b[1]));
}

#define APAD 36
#define BPAD 136

__device__ __forceinline__ void cvt_store4(uint32_t* dst, float4 v) {
    uint4 t;
    t.x = f2tf32(v.x); t.y = f2tf32(v.y); t.z = f2tf32(v.z); t.w = f2tf32(v.w);
    *(uint4*)dst = t;
}

// ---------------------------------------------------------------------------
// tf32 MMA GEMM body (R12 measured-best: single-buffer + register prefetch).
// ---------------------------------------------------------------------------
struct GemmRegs { float d[2][8][4]; };

template <bool QKV>
__device__ __forceinline__ void gemm_mma_body(
    GemmRegs& R, uint32_t* As, uint32_t* Bs,
    const float* __restrict__ W, const float* __restrict__ x,
    int o0, int p0, int tid)
{
    const int lane = tid & 31, wid = tid >> 5;
    const int gid = lane >> 2, tg = lane & 3;
    const int wm = wid & 3, wn = wid >> 2;
    const int rbase = wm * 32, cbase = wn * 64;

    #pragma unroll
    for (int t = 0; t < 2; t++)
        #pragma unroll
        for (int j = 0; j < 8; j++)
            #pragma unroll
            for (int q = 0; q < 4; q++) R.d[t][j][q] = 0.f;

    const int bk  = tid >> 3;
    const int bpx = (tid & 7) * 16;
    const float* bsrc;
    if (QKV) {
        const int P16 = p0 + bpx;
        const int bt  = (P16 >= HW) ? 1 : 0;
        bsrc = x + (size_t)bt * DM * HW + (size_t)bk * HW + (P16 - bt * HW);
    } else {
        bsrc = g_a + (size_t)bk * PTOT + p0 + bpx;
    }
    const size_t brstride = QKV ? (size_t)HW : (size_t)PTOT;

    const int ao = tid >> 1;
    const int akq = (tid & 1) * 16;
    const float* arow0 = W + (size_t)(o0 + ao) * DM + akq;

    float4 aR[4], bR[4];
    #pragma unroll
    for (int i = 0; i < 4; i++) aR[i] = ((const float4*)arow0)[i];
    #pragma unroll
    for (int i = 0; i < 4; i++) bR[i] = ((const float4*)bsrc)[i];

    for (int kc = 0; kc < 8; kc++) {
        #pragma unroll
        for (int i = 0; i < 4; i++)
            cvt_store4(&As[ao * APAD + akq + i * 4], aR[i]);
        #pragma unroll
        for (int i = 0; i < 4; i++)
            cvt_store4(&Bs[bk * BPAD + bpx + i * 4], bR[i]);
        __syncthreads();

        if (kc < 7) {
            const float* ar = arow0 + (kc + 1) * 32;
            const float* br = bsrc + (size_t)((kc + 1) * 32) * brstride;
            #pragma unroll
            for (int i = 0; i < 4; i++) aR[i] = ((const float4*)ar)[i];
            #pragma unroll
            for (int i = 0; i < 4; i++) bR[i] = ((const float4*)br)[i];
        }

        #pragma unroll
        for (int kk = 0; kk < 4; kk++) {
            const int kb = kk * 8;
            uint32_t a[2][4];
            #pragma unroll
            for (int t = 0; t < 2; t++) {
                const int r0 = rbase + t * 16 + gid;
                a[t][0] = As[(r0)     * APAD + kb + tg];
                a[t][1] = As[(r0 + 8) * APAD + kb + tg];
                a[t][2] = As[(r0)     * APAD + kb + tg + 4];
                a[t][3] = As[(r0 + 8) * APAD + kb + tg + 4];
            }
            uint32_t b[8][2];
            #pragma unroll
            for (int j = 0; j < 8; j++) {
                const int col = cbase + j * 8 + gid;
                b[j][0] = Bs[(kb + tg)     * BPAD + col];
                b[j][1] = Bs[(kb + tg + 4) * BPAD + col];
            }
            #pragma unroll
            for (int t = 0; t < 2; t++)
                #pragma unroll
                for (int j = 0; j < 8; j++)
                    mma_tf32(R.d[t][j], a[t], b[j]);
        }
        __syncthreads();
    }
}

// ---------------------------------------------------------------------------
__global__ __launch_bounds__(256, 2) void qkv_mma_kernel(
    const float* __restrict__ x,
    const float* __restrict__ wq, const float* __restrict__ bq,
    const float* __restrict__ wk, const float* __restrict__ bk,
    const float* __restrict__ wv, const float* __restrict__ bv)
{
    __shared__ __align__(16) uint32_t As[128 * APAD];
    __shared__ __align__(16) uint32_t Bs[32 * BPAD];

    const int m = blockIdx.z;
    const float* __restrict__ W    = (m == 0) ? wq : (m == 1) ? wk : wv;
    const float* __restrict__ bias = (m == 0) ? bq : (m == 1) ? bk : bv;
    float* __restrict__ out        = (m == 0) ? g_q : (m == 1) ? g_k : g_v;

    const int p0 = blockIdx.x * 128;
    const int o0 = blockIdx.y * 128;
    const int tid = threadIdx.x;

    GemmRegs R;
    gemm_mma_body<true>(R, As, Bs, W, x, o0, p0, tid);

    const int lane = tid & 31, wid = tid >> 5;
    const int gid = lane >> 2, tg = lane & 3;
    const int wm = wid & 3, wn = wid >> 2;
    #pragma unroll
    for (int t = 0; t < 2; t++) {
        const int orow = o0 + wm * 32 + t * 16 + gid;
        const float b0 = bias[orow], b1 = bias[orow + 8];
        #pragma unroll
        for (int j = 0; j < 8; j++) {
            const int px = p0 + wn * 64 + j * 8 + 2 * tg;
            *(float2*)(out + (size_t)orow * PTOT + px) =
                make_float2(R.d[t][j][0] + b0, R.d[t][j][1] + b0);
            *(float2*)(out + (size_t)(orow + 8) * PTOT + px) =
                make_float2(R.d[t][j][2] + b1, R.d[t][j][3] + b1);
        }
    }
}

__global__ __launch_bounds__(256, 2) void oproj_mma_kernel(
    const float* __restrict__ wo, const float* __restrict__ bo,
    float* __restrict__ outp)
{
    __shared__ __align__(16) uint32_t As[128 * APAD];
    __shared__ __align__(16) uint32_t Bs[32 * BPAD];

    const int p0 = blockIdx.x * 128;
    const int o0 = blockIdx.y * 128;
    const int tid = threadIdx.x;

    GemmRegs R;
    gemm_mma_body<false>(R, As, Bs, wo, nullptr, o0, p0, tid);

    const int lane = tid & 31, wid = tid >> 5;
    const int gid = lane >> 2, tg = lane & 3;
    const int wm = wid & 3, wn = wid >> 2;
    #pragma unroll
    for (int t = 0; t < 2; t++) {
        const int orow = o0 + wm * 32 + t * 16 + gid;
        const float b0 = bo[orow], b1 = bo[orow + 8];
        #pragma unroll
        for (int j = 0; j < 8; j++) {
            const int P8 = p0 + wn * 64 + j * 8;
            const int bt = (P8 >= HW) ? 1 : 0;
            const int px = P8 - bt * HW + 2 * tg;
            float* d0 = outp + ((size_t)bt * DM + orow) * HW + px;
            float* d1 = outp + ((size_t)bt * DM + orow + 8) * HW + px;
            *(float2*)d0 = make_float2(R.d[t][j][0] + b0, R.d[t][j][1] + b0);
            *(float2*)d1 = make_float2(R.d[t][j][2] + b1, R.d[t][j][3] + b1);
        }
    }
}

// ---------------------------------------------------------------------------
// Attention, 3-kernel d-split. Tile = 4 rows x 56 cols, 2 px/thread,
// block 128 (112 active). Score/out grids: (14, 16, 2) = 448 blocks.
// ---------------------------------------------------------------------------
#define SROWS 10
#define SLICE4 (SROWS * 64)       // 640
#define PIPE 4

struct AttnIdx {
    int r, x0, p, at;
    bool act;
    int  goff[5];
    bool gok[5];
    uint32_t dby[5];
};

__device__ __forceinline__ AttnIdx attn_idx(int y0, int tid) {
    AttnIdx ix;
    ix.act = (tid < 112);
    ix.r   = ix.act ? (tid / 28) : 3;
    const int xp = ix.act ? (tid - (tid / 28) * 28) : 0;
    ix.x0  = xp * 2;
    ix.p   = (y0 + ix.r) * 56 + ix.x0;
    ix.at  = ix.r * 28 + xp;
    #pragma unroll
    for (int it = 0; it < 5; it++) {
        int idx = tid + it * 128;
        int row = idx >> 6;
        int col = idx & 63;
        int gy = y0 - 3 + row;
        int gx = col - 3;
        ix.gok[it]  = ((unsigned)gy < 56u) && ((unsigned)gx < 56u);
        ix.goff[it] = ix.gok[it] ? (gy * 56 + gx) : 0;
        ix.dby[it]  = (uint32_t)idx * 4u;
    }
    return ix;
}

// ---- Kernel 1: partial scores over 16 d ----
__global__ __launch_bounds__(128) void attn_score_kernel()
{
    const int z   = blockIdx.y;
    const int g   = blockIdx.z;
    const int b   = z >> 3;
    const int h   = z & 7;
    const int y0  = blockIdx.x * 4;
    const int tid = threadIdx.x;
    AttnIdx ix = attn_idx(y0, tid);

    const size_t base = (size_t)(h * HD + g * 16) * PTOT + (size_t)b * HW;
    const float* __restrict__ qbase = g_q + base;
    const float* __restrict__ kbase = g_k + base;

    __shared__ __align__(16) float sk[PIPE][2][SLICE4];
    const uint32_t skb = smem_u32(sk);

    const u64 scale2 = pack2s(0.17677669529663687f);

    u64 s01[NW];
    #pragma unroll
    for (int i = 0; i < NW; i++) s01[i] = 0ull;

    #pragma unroll
    for (int s = 0; s < PIPE - 1; s++) {
        const float* gA = kbase + (size_t)(2 * s) * PTOT;
        const float* gB = gA + PTOT;
        const uint32_t sb = skb + (uint32_t)s * (2 * SLICE4 * 4);
        #pragma unroll
        for (int it = 0; it < 5; it++) {
            cpa4(sb + ix.dby[it], gA + ix.goff[it], ix.gok[it]);
            cpa4(sb + SLICE4 * 4 + ix.dby[it], gB + ix.goff[it], ix.gok[it]);
        }
        CPA_COMMIT();
    }

    float2 qa_n = *(const float2*)(qbase + ix.p);
    float2 qb_n = *(const float2*)(qbase + PTOT + ix.p);

    for (int i = 0; i < 8; i++) {
        CPA_WAIT2();
        __syncthreads();
        if (i + 3 < 8) {
            const int s = i + 3;
            const float* gA = kbase + (size_t)(2 * s) * PTOT;
            const float* gB = gA + PTOT;
            const uint32_t sb = skb + (uint32_t)(s & 3) * (2 * SLICE4 * 4);
            #pragma unroll
            for (int it = 0; it < 5; it++) {
                cpa4(sb + ix.dby[it], gA + ix.goff[it], ix.gok[it]);
                cpa4(sb + SLICE4 * 4 + ix.dby[it], gB + ix.goff[it], ix.gok[it]);
            }
        }
        CPA_COMMIT();

        float2 qa = qa_n, qb = qb_n;
        if (i + 1 < 8) {
            qa_n = *(const float2*)(qbase + (size_t)(2 * i + 2) * PTOT + ix.p);
            qb_n = *(const float2*)(qbase + (size_t)(2 * i + 3) * PTOT + ix.p);
        }
        const u64 qA = mul2(packpair(qa.x, qa.y), scale2);
        const u64 qB = mul2(packpair(qb.x, qb.y), scale2);

        const float* slA = &sk[i & 3][0][ix.r * 64 + ix.x0];
        const float* slB = &sk[i & 3][1][ix.r * 64 + ix.x0];
        #pragma unroll
        for (int dy = 0; dy < WS; dy++) {
            float ka[8], kb[8];
            #pragma unroll
            for (int q = 0; q < 4; q++) {
                float2 ta = *(const float2*)(slA + dy * 64 + 2 * q);
                float2 tb = *(const float2*)(slB + dy * 64 + 2 * q);
                ka[2*q] = ta.x; ka[2*q+1] = ta.y;
                kb[2*q] = tb.x; kb[2*q+1] = tb.y;
            }
            #pragma unroll
            for (int dx = 0; dx < WS; dx++) {
                ffma2(s01[dy * WS + dx], qA, packpair(ka[dx], ka[dx + 1]));
                ffma2(s01[dy * WS + dx], qB, packpair(kb[dx], kb[dx + 1]));
            }
        }
    }

    if (ix.act) {
        const size_t sbase = (size_t)g * SLABSZ
                           + ((size_t)(z * 14 + blockIdx.x) * NW) * 112 + ix.at;
        #pragma unroll
        for (int i = 0; i < NW; i++)
            g_sc[sbase + (size_t)i * 112] = s01[i];
    }
}

// ---- Kernel 2: reduce partials + softmax -> probs in slab 0 ----
__global__ __launch_bounds__(256) void attn_soft_kernel()
{
    const int t  = blockIdx.x * 256 + threadIdx.x;   // 0..25087
    const int at = t % 112;
    const int r2 = t / 112;
    const size_t base = ((size_t)r2 * NW) * 112 + at;

    u64 s[NW];
    float e0[NW], e1[NW];
    float mx0 = -1e30f, mx1 = -1e30f;
    #pragma unroll
    for (int i = 0; i < NW; i++) {
        s[i] = add2(g_sc[base + (size_t)i * 112], g_sc[SLABSZ + base + (size_t)i * 112]);
        float2 v = unpack2(s[i]);
        mx0 = fmaxf(mx0, v.x); mx1 = fmaxf(mx1, v.y);
    }
    float sum0 = 0.f, sum1 = 0.f;
    #pragma unroll
    for (int i = 0; i < NW; i++) {
        float2 v = unpack2(s[i]);
        e0[i] = __expf(v.x - mx0); sum0 += e0[i];
        e1[i] = __expf(v.y - mx1); sum1 += e1[i];
    }
    const float inv0 = 1.f / sum0;
    const float inv1 = 1.f / sum1;
    #pragma unroll
    for (int i = 0; i < NW; i++)
        g_sc[base + (size_t)i * 112] = packpair(e0[i] * inv0, e1[i] * inv1);
}

// ---- Kernel 3: output over 16 d ----
__global__ __launch_bounds__(128) void attn_out_kernel()
{
    const int z   = blockIdx.y;
    const int g   = blockIdx.z;
    const int b   = z >> 3;
    const int h   = z & 7;
    const int y0  = blockIdx.x * 4;
    const int tid = threadIdx.x;
    AttnIdx ix = attn_idx(y0, tid);

    const size_t base = (size_t)(h * HD + g * 16) * PTOT + (size_t)b * HW;
    const float* __restrict__ vbase = g_v + base;
    float*       __restrict__ abase = g_a + base;

    __shared__ __align__(16) float sk[PIPE][2][SLICE4];
    const uint32_t skb = smem_u32(sk);

    // Load probabilities.
    u64 s01[NW];
    {
        const size_t sbase = ((size_t)(z * 14 + blockIdx.x) * NW) * 112 + ix.at;
        #pragma unroll
        for (int i = 0; i < NW; i++)
            s01[i] = g_sc[sbase + (size_t)i * 112];
    }

    #pragma unroll
    for (int s = 0; s < PIPE - 1; s++) {
        const float* gA = vbase + (size_t)(2 * s) * PTOT;
        const float* gB = gA + PTOT;
        const uint32_t sb = skb + (uint32_t)s * (2 * SLICE4 * 4);
        #pragma unroll
        for (int it = 0; it < 5; it++) {
            cpa4(sb + ix.dby[it], gA + ix.goff[it], ix.gok[it]);
            cpa4(sb + SLICE4 * 4 + ix.dby[it], gB + ix.goff[it], ix.gok[it]);
        }
        CPA_COMMIT();
    }

    for (int i = 0; i < 8; i++) {
        CPA_WAIT2();
        __syncthreads();
        if (i + 3 < 8) {
            const int s = i + 3;
            const float* gA = vbase + (size_t)(2 * s) * PTOT;
            const float* gB = gA + PTOT;
            const uint32_t sb = skb + (uint32_t)(s & 3) * (2 * SLICE4 * 4);
            #pragma unroll
            for (int it = 0; it < 5; it++) {
                cpa4(sb + ix.dby[it], gA + ix.goff[it], ix.gok[it]);
                cpa4(sb + SLICE4 * 4 + ix.dby[it], gB + ix.goff[it], ix.gok[it]);
            }
        }
        CPA_COMMIT();

        u64 accA = 0ull, accB = 0ull;
        const float* slA = &sk[i & 3][0][ix.r * 64 + ix.x0];
        const float* slB = &sk[i & 3][1][ix.r * 64 + ix.x0];
        #pragma unroll
        for (int dy = 0; dy < WS; dy++) {
            float ka[8], kb[8];
            #pragma unroll
            for (int q = 0; q < 4; q++) {
                float2 ta = *(const float2*)(slA + dy * 64 + 2 * q);
                float2 tb = *(const float2*)(slB + dy * 64 + 2 * q);
                ka[2*q] = ta.x; ka[2*q+1] = ta.y;
                kb[2*q] = tb.x; kb[2*q+1] = tb.y;
            }
            #pragma unroll
            for (int dx = 0; dx < WS; dx++) {
                ffma2(accA, s01[dy * WS + dx], packpair(ka[dx], ka[dx + 1]));
                ffma2(accB, s01[dy * WS + dx], packpair(kb[dx], kb[dx + 1]));
            }
        }
        if (ix.act) {
            *(float2*)(abase + (size_t)(2 * i) * PTOT + ix.p)     = unpack2(accA);
            *(float2*)(abase + (size_t)(2 * i + 1) * PTOT + ix.p) = unpack2(accB);
        }
    }
}

// ---------------------------------------------------------------------------
extern "C" void kernel_launch(void* const* d_in, const int* in_sizes, int n_in,
                              void* d_out, int out_size)
{
    (void)in_sizes; (void)n_in; (void)out_size;
    const float* x  = (const float*)d_in[0];
    const float* wq = (const float*)d_in[1];
    const float* bq = (const float*)d_in[2];
    const float* wk = (const float*)d_in[3];
    const float* bk = (const float*)d_in[4];
    const float* wv = (const float*)d_in[5];
    const float* bv = (const float*)d_in[6];
    const float* wo = (const float*)d_in[7];
    const float* bo = (const float*)d_in[8];
    float* out = (float*)d_out;

    qkv_mma_kernel<<<dim3(PTOT / 128, DM / 128, 3), 256>>>(x, wq, bq, wk, bk, wv, bv);
    attn_score_kernel<<<dim3(14, NB * NH, 2), 128>>>();
    attn_soft_kernel<<<98, 256>>>();
    attn_out_kernel<<<dim3(14, NB * NH, 2), 128>>>();
    oproj_mma_kernel<<<dim3(PTOT / 128, DM / 128), 256>>>(wo, bo, out);
}

// round 15
// speedup vs baseline: 1.1555x; 1.1555x over previous
#include <cuda_runtime.h>
#include <cuda_bf16.h>
#include <cstdint>

// Problem constants
#define DM     256
#define HW     3136
#define NB     2
#define PTOT   (NB*HW)       // 6272 = 49*128 (fused pixel axis)
#define NH     8
#define HD     32
#define WS     7
#define NW     49

// Scratch (device globals). Fused layout: [c][P] with c = h*32+d, P = b*HW+p.
__device__ float g_q[DM * PTOT];
__device__ float g_k[DM * PTOT];
__device__ float g_v[DM * PTOT];
__device__ float g_a[DM * PTOT];

// Pre-converted tf32 weights in MMA fragment layout.
// uint4 index: (oi*4+wm)*2048 + kc*256 + kk*64 + t*32 + lane
// holds {W[r][c], W[r+8][c], W[r][c+4], W[r+8][c+4]} as tf32 with
// r = oi*128 + wm*32 + t*16 + (lane>>2), c = kc*32 + kk*8 + (lane&3).
__device__ uint4 g_wf[4][16384];   // q,k,v,o — 1 MB total

typedef unsigned long long u64;
// ---- packed f32x2 helpers (attention) -------------------------------------
__device__ __forceinline__ u64 pack2s(float v) {
    u64 r; asm("mov.b64 %0, {%1, %1};" : "=l"(r) : "f"(v)); return r;
}
__device__ __forceinline__ u64 packpair(float a, float b) {
    u64 r; asm("mov.b64 %0, {%1, %2};" : "=l"(r) : "f"(a), "f"(b)); return r;
}
__device__ __forceinline__ void ffma2(u64& d, u64 a, u64 b) {
    asm("fma.rn.f32x2 %0, %1, %2, %0;" : "+l"(d) : "l"(a), "l"(b));
}
__device__ __forceinline__ u64 mul2(u64 a, u64 b) {
    u64 r; asm("mul.rn.f32x2 %0, %1, %2;" : "=l"(r) : "l"(a), "l"(b)); return r;
}
__device__ __forceinline__ float2 unpack2(u64 v) {
    float2 r; asm("mov.b64 {%0, %1}, %2;" : "=f"(r.x), "=f"(r.y) : "l"(v)); return r;
}

// ---- cp.async helpers -------------------------------------------------------
__device__ __forceinline__ uint32_t smem_u32(const void* p) {
    uint32_t a;
    asm("{ .reg .u64 t; cvta.to.shared.u64 t, %1; cvt.u32.u64 %0, t; }" : "=r"(a) : "l"(p));
    return a;
}
__device__ __forceinline__ void cpa4(uint32_t dst, const float* src, bool ok) {
    asm volatile("cp.async.ca.shared.global [%0], [%1], 4, %2;"
        :: "r"(dst), "l"(src), "r"(ok ? 4u : 0u) : "memory");
}
#define CPA_COMMIT() asm volatile("cp.async.commit_group;" ::: "memory")
#define CPA_WAIT2()  asm volatile("cp.async.wait_group 2;" ::: "memory")

// ---- tf32 mma helpers ------------------------------------------------------
__device__ __forceinline__ uint32_t f2tf32(float v) {
    uint32_t r; asm("cvt.rna.tf32.f32 %0, %1;" : "=r"(r) : "f"(v)); return r;
}
__device__ __forceinline__ void mma_tf32(float* d, const uint32_t* a, const uint32_t* b) {
    asm volatile(
        "mma.sync.aligned.m16n8k8.row.col.f32.tf32.tf32.f32 "
        "{%0,%1,%2,%3}, {%4,%5,%6,%7}, {%8,%9}, {%0,%1,%2,%3};"
        : "+f"(d[0]), "+f"(d[1]), "+f"(d[2]), "+f"(d[3])
        : "r"(a[0]), "r"(a[1]), "r"(a[2]), "r"(a[3]), "r"(b[0]), "r"(b[1]));
}

#define BPAD 136

__device__ __forceinline__ void cvt_store4(uint32_t* dst, float4 v) {
    uint4 t;
    t.x = f2tf32(v.x); t.y = f2tf32(v.y); t.z = f2tf32(v.z); t.w = f2tf32(v.w);
    *(uint4*)dst = t;
}

// ---------------------------------------------------------------------------
// Prepass: convert 4 weight matrices to fragment-layout tf32.
// grid 256 x 256 threads; one thread -> one uint4.
// ---------------------------------------------------------------------------
__global__ __launch_bounds__(256) void wfrag_kernel(
    const float* __restrict__ wq, const float* __restrict__ wk,
    const float* __restrict__ wv, const float* __restrict__ wo)
{
    const int gidx = blockIdx.x * 256 + threadIdx.x;   // 0..65535
    const int m = gidx >> 14;
    const int rI = gidx & 16383;
    const float* W = (m == 0) ? wq : (m == 1) ? wk : (m == 2) ? wv : wo;

    const int lane = rI & 31;
    const int t    = (rI >> 5) & 1;
    const int kk   = (rI >> 6) & 3;
    const int kc   = (rI >> 8) & 7;
    const int wm   = (rI >> 11) & 3;
    const int oi   = (rI >> 13) & 1;

    const int row = oi * 128 + wm * 32 + t * 16 + (lane >> 2);
    const int col = kc * 32 + kk * 8 + (lane & 3);

    uint4 v;
    v.x = f2tf32(W[(size_t)row * DM + col]);
    v.y = f2tf32(W[(size_t)(row + 8) * DM + col]);
    v.z = f2tf32(W[(size_t)row * DM + col + 4]);
    v.w = f2tf32(W[(size_t)(row + 8) * DM + col + 4]);
    g_wf[m][rI] = v;
}

// ---------------------------------------------------------------------------
// tf32 MMA GEMM body: A frags streamed from fragment-layout gmem (L2-hot),
// B staged in smem with register prefetch. Block 256 = 8 warps (4m x 2n).
// ---------------------------------------------------------------------------
struct GemmRegs { float d[2][8][4]; };

template <bool QKV>
__device__ __forceinline__ void gemm_mma_body(
    GemmRegs& R, uint32_t* Bs,
    const uint4* __restrict__ wf,       // matrix's fragment array
    const float* __restrict__ x,        // used iff QKV
    int o0, int p0, int tid)
{
    const int lane = tid & 31, wid = tid >> 5;
    const int gid = lane >> 2, tg = lane & 3;
    const int wm = wid & 3, wn = wid >> 2;
    const int cbase = wn * 64;
    const int oi = o0 >> 7;

    const uint4* __restrict__ afb = wf + ((oi * 4 + wm) * 2048 + lane);

    #pragma unroll
    for (int t = 0; t < 2; t++)
        #pragma unroll
        for (int j = 0; j < 8; j++)
            #pragma unroll
            for (int q = 0; q < 4; q++) R.d[t][j][q] = 0.f;

    const int bk  = tid >> 3;
    const int bpx = (tid & 7) * 16;
    const float* bsrc;
    if (QKV) {
        const int P16 = p0 + bpx;
        const int bt  = (P16 >= HW) ? 1 : 0;
        bsrc = x + (size_t)bt * DM * HW + (size_t)bk * HW + (P16 - bt * HW);
    } else {
        bsrc = g_a + (size_t)bk * PTOT + p0 + bpx;
    }
    const size_t brstride = QKV ? (size_t)HW : (size_t)PTOT;

    float4 bR[4];
    #pragma unroll
    for (int i = 0; i < 4; i++) bR[i] = ((const float4*)bsrc)[i];

    for (int kc = 0; kc < 8; kc++) {
        #pragma unroll
        for (int i = 0; i < 4; i++)
            cvt_store4(&Bs[bk * BPAD + bpx + i * 4], bR[i]);
        __syncthreads();

        if (kc < 7) {
            const float* br = bsrc + (size_t)((kc + 1) * 32) * brstride;
            #pragma unroll
            for (int i = 0; i < 4; i++) bR[i] = ((const float4*)br)[i];
        }

        // A fragments for this chunk: 8 coalesced LDG.128 from L2.
        uint4 aF[8];
        {
            const uint4* af = afb + kc * 256;
            #pragma unroll
            for (int kk = 0; kk < 4; kk++) {
                aF[kk * 2]     = af[kk * 64];
                aF[kk * 2 + 1] = af[kk * 64 + 32];
            }
        }

        #pragma unroll
        for (int kk = 0; kk < 4; kk++) {
            const int kb = kk * 8;
            uint32_t b[8][2];
            #pragma unroll
            for (int j = 0; j < 8; j++) {
                const int col = cbase + j * 8 + gid;
                b[j][0] = Bs[(kb + tg)     * BPAD + col];
                b[j][1] = Bs[(kb + tg + 4) * BPAD + col];
            }
            #pragma unroll
            for (int t = 0; t < 2; t++)
                #pragma unroll
                for (int j = 0; j < 8; j++)
                    mma_tf32(R.d[t][j], (const uint32_t*)&aF[kk * 2 + t], b[j]);
        }
        __syncthreads();
    }
}

// ---------------------------------------------------------------------------
// QKV MMA GEMM. grid (49, 2, 3), block 256.
// ---------------------------------------------------------------------------
__global__ __launch_bounds__(256, 2) void qkv_mma_kernel(
    const float* __restrict__ x,
    const float* __restrict__ bq, const float* __restrict__ bk,
    const float* __restrict__ bv)
{
    __shared__ __align__(16) uint32_t Bs[32 * BPAD];

    const int m = blockIdx.z;
    const float* __restrict__ bias = (m == 0) ? bq : (m == 1) ? bk : bv;
    float* __restrict__ out        = (m == 0) ? g_q : (m == 1) ? g_k : g_v;

    const int p0 = blockIdx.x * 128;
    const int o0 = blockIdx.y * 128;
    const int tid = threadIdx.x;

    GemmRegs R;
    gemm_mma_body<true>(R, Bs, g_wf[m], x, o0, p0, tid);

    const int lane = tid & 31, wid = tid >> 5;
    const int gid = lane >> 2, tg = lane & 3;
    const int wm = wid & 3, wn = wid >> 2;
    #pragma unroll
    for (int t = 0; t < 2; t++) {
        const int orow = o0 + wm * 32 + t * 16 + gid;
        const float b0 = bias[orow], b1 = bias[orow + 8];
        #pragma unroll
        for (int j = 0; j < 8; j++) {
            const int px = p0 + wn * 64 + j * 8 + 2 * tg;
            *(float2*)(out + (size_t)orow * PTOT + px) =
                make_float2(R.d[t][j][0] + b0, R.d[t][j][1] + b0);
            *(float2*)(out + (size_t)(orow + 8) * PTOT + px) =
                make_float2(R.d[t][j][2] + b1, R.d[t][j][3] + b1);
        }
    }
}

// ---------------------------------------------------------------------------
// O-proj MMA GEMM. grid (49, 2), block 256. Direct write + bias + batch unfuse.
// ---------------------------------------------------------------------------
__global__ __launch_bounds__(256, 2) void oproj_mma_kernel(
    const float* __restrict__ bo, float* __restrict__ outp)
{
    __shared__ __align__(16) uint32_t Bs[32 * BPAD];

    const int p0 = blockIdx.x * 128;
    const int o0 = blockIdx.y * 128;
    const int tid = threadIdx.x;

    GemmRegs R;
    gemm_mma_body<false>(R, Bs, g_wf[3], nullptr, o0, p0, tid);

    const int lane = tid & 31, wid = tid >> 5;
    const int gid = lane >> 2, tg = lane & 3;
    const int wm = wid & 3, wn = wid >> 2;
    #pragma unroll
    for (int t = 0; t < 2; t++) {
        const int orow = o0 + wm * 32 + t * 16 + gid;
        const float b0 = bo[orow], b1 = bo[orow + 8];
        #pragma unroll
        for (int j = 0; j < 8; j++) {
            const int P8 = p0 + wn * 64 + j * 8;
            const int bt = (P8 >= HW) ? 1 : 0;
            const int px = P8 - bt * HW + 2 * tg;
            float* d0 = outp + ((size_t)bt * DM + orow) * HW + px;
            float* d1 = outp + ((size_t)bt * DM + orow + 8) * HW + px;
            *(float2*)d0 = make_float2(R.d[t][j][0] + b0, R.d[t][j][1] + b0);
            *(float2*)d1 = make_float2(R.d[t][j][2] + b1, R.d[t][j][3] + b1);
        }
    }
}

// ---------------------------------------------------------------------------
// Windowed attention (R12 measured-best): 4x56 tiles, 2 px/thread, packed
// f32x2 scores, 4-deep cp.async pipeline. grid (14, 16), block 128.
// ---------------------------------------------------------------------------
#define SROWS 10
#define SLICE4 (SROWS * 64)       // 640
#define PIPE 4

__global__ __launch_bounds__(128) void attn_kernel()
{
    const int z   = blockIdx.y;
    const int b   = z >> 3;
    const int h   = z & 7;
    const int y0  = blockIdx.x * 4;
    const int tid = threadIdx.x;
    const bool act = (tid < 112);
    const int r   = act ? (tid / 28) : 3;
    const int xp  = act ? (tid - (tid / 28) * 28) : 0;
    const int x0  = xp * 2;
    const int p   = (y0 + r) * 56 + x0;

    const size_t base = (size_t)(h * HD) * PTOT + (size_t)b * HW;
    const float* __restrict__ qbase = g_q + base;
    const float* __restrict__ kbase = g_k + base;
    const float* __restrict__ vbase = g_v + base;
    float*       __restrict__ abase = g_a + base;

    __shared__ __align__(16) float sk[PIPE][2][SLICE4];
    const uint32_t skb = smem_u32(sk);

    int  goff[5];
    bool gok[5];
    uint32_t dby[5];
    #pragma unroll
    for (int it = 0; it < 5; it++) {
        int idx = tid + it * 128;
        int row = idx >> 6;
        int col = idx & 63;
        int gy = y0 - 3 + row;
        int gx = col - 3;
        gok[it]  = ((unsigned)gy < 56u) && ((unsigned)gx < 56u);
        goff[it] = gok[it] ? (gy * 56 + gx) : 0;
        dby[it]  = (uint32_t)idx * 4u;
    }

    const u64 scale2 = pack2s(0.17677669529663687f);

    u64 s01[NW];
    #pragma unroll
    for (int i = 0; i < NW; i++) s01[i] = 0ull;

    // ---- Phase 1: scores (K pipeline) ----
    #pragma unroll
    for (int s = 0; s < PIPE - 1; s++) {
        const float* gA = kbase + (size_t)(2 * s) * PTOT;
        const float* gB = gA + PTOT;
        const uint32_t sb = skb + (uint32_t)s * (2 * SLICE4 * 4);
        #pragma unroll
        for (int it = 0; it < 5; it++) {
            cpa4(sb + dby[it], gA + goff[it], gok[it]);
            cpa4(sb + SLICE4 * 4 + dby[it], gB + goff[it], gok[it]);
        }
        CPA_COMMIT();
    }

    float2 qa_n = *(const float2*)(qbase + p);
    float2 qb_n = *(const float2*)(qbase + PTOT + p);

    for (int i = 0; i < 16; i++) {
        CPA_WAIT2();
        __syncthreads();
        if (i + 3 < 16) {
            const int s = i + 3;
            const float* gA = kbase + (size_t)(2 * s) * PTOT;
            const float* gB = gA + PTOT;
            const uint32_t sb = skb + (uint32_t)(s & 3) * (2 * SLICE4 * 4);
            #pragma unroll
            for (int it = 0; it < 5; it++) {
                cpa4(sb + dby[it], gA + goff[it], gok[it]);
                cpa4(sb + SLICE4 * 4 + dby[it], gB + goff[it], gok[it]);
            }
        }
        CPA_COMMIT();

        float2 qa = qa_n, qb = qb_n;
        if (i + 1 < 16) {
            qa_n = *(const float2*)(qbase + (size_t)(2 * i + 2) * PTOT + p);
            qb_n = *(const float2*)(qbase + (size_t)(2 * i + 3) * PTOT + p);
        }
        const u64 qA = mul2(packpair(qa.x, qa.y), scale2);
        const u64 qB = mul2(packpair(qb.x, qb.y), scale2);

        const float* slA = &sk[i & 3][0][r * 64 + x0];
        const float* slB = &sk[i & 3][1][r * 64 + x0];
        #pragma unroll
        for (int dy = 0; dy < WS; dy++) {
            float ka[8], kb[8];
            #pragma unroll
            for (int q = 0; q < 4; q++) {
                float2 ta = *(const float2*)(slA + dy * 64 + 2 * q);
                float2 tb = *(const float2*)(slB + dy * 64 + 2 * q);
                ka[2*q] = ta.x; ka[2*q+1] = ta.y;
                kb[2*q] = tb.x; kb[2*q+1] = tb.y;
            }
            #pragma unroll
            for (int dx = 0; dx < WS; dx++) {
                ffma2(s01[dy * WS + dx], qA, packpair(ka[dx], ka[dx + 1]));
                ffma2(s01[dy * WS + dx], qB, packpair(kb[dx], kb[dx + 1]));
            }
        }
    }

    // ---- Softmax ----
    {
        float mx0, mx1;
        {
            float2 t = unpack2(s01[0]);
            mx0 = t.x; mx1 = t.y;
        }
        #pragma unroll
        for (int i = 1; i < NW; i++) {
            float2 t = unpack2(s01[i]);
            mx0 = fmaxf(mx0, t.x); mx1 = fmaxf(mx1, t.y);
        }
        float sum0 = 0.f, sum1 = 0.f;
        float e0[NW], e1[NW];
        #pragma unroll
        for (int i = 0; i < NW; i++) {
            float2 t = unpack2(s01[i]);
            e0[i] = __expf(t.x - mx0); sum0 += e0[i];
            e1[i] = __expf(t.y - mx1); sum1 += e1[i];
        }
        const float inv0 = 1.f / sum0;
        const float inv1 = 1.f / sum1;
        #pragma unroll
        for (int i = 0; i < NW; i++)
            s01[i] = packpair(e0[i] * inv0, e1[i] * inv1);
    }

    // ---- Phase 2: output (V pipeline) ----
    asm volatile("cp.async.wait_group 0;" ::: "memory");
    __syncthreads();
    #pragma unroll
    for (int s = 0; s < PIPE - 1; s++) {
        const float* gA = vbase + (size_t)(2 * s) * PTOT;
        const float* gB = gA + PTOT;
        const uint32_t sb = skb + (uint32_t)s * (2 * SLICE4 * 4);
        #pragma unroll
        for (int it = 0; it < 5; it++) {
            cpa4(sb + dby[it], gA + goff[it], gok[it]);
            cpa4(sb + SLICE4 * 4 + dby[it], gB + goff[it], gok[it]);
        }
        CPA_COMMIT();
    }

    for (int i = 0; i < 16; i++) {
        CPA_WAIT2();
        __syncthreads();
        if (i + 3 < 16) {
            const int s = i + 3;
            const float* gA = vbase + (size_t)(2 * s) * PTOT;
            const float* gB = gA + PTOT;
            const uint32_t sb = skb + (uint32_t)(s & 3) * (2 * SLICE4 * 4);
            #pragma unroll
            for (int it = 0; it < 5; it++) {
                cpa4(sb + dby[it], gA + goff[it], gok[it]);
                cpa4(sb + SLICE4 * 4 + dby[it], gB + goff[it], gok[it]);
            }
        }
        CPA_COMMIT();

        u64 accA = 0ull, accB = 0ull;
        const float* slA = &sk[i & 3][0][r * 64 + x0];
        const float* slB = &sk[i & 3][1][r * 64 + x0];
        #pragma unroll
        for (int dy = 0; dy < WS; dy++) {
            float ka[8], kb[8];
            #pragma unroll
            for (int q = 0; q < 4; q++) {
                float2 ta = *(const float2*)(slA + dy * 64 + 2 * q);
                float2 tb = *(const float2*)(slB + dy * 64 + 2 * q);
                ka[2*q] = ta.x; ka[2*q+1] = ta.y;
                kb[2*q] = tb.x; kb[2*q+1] = tb.y;
            }
            #pragma unroll
            for (int dx = 0; dx < WS; dx++) {
                ffma2(accA, s01[dy * WS + dx], packpair(ka[dx], ka[dx + 1]));
                ffma2(accB, s01[dy * WS + dx], packpair(kb[dx], kb[dx + 1]));
            }
        }
        if (act) {
            *(float2*)(abase + (size_t)(2 * i) * PTOT + p)     = unpack2(accA);
            *(float2*)(abase + (size_t)(2 * i + 1) * PTOT + p) = unpack2(accB);
        }
    }
}

// ---------------------------------------------------------------------------
extern "C" void kernel_launch(void* const* d_in, const int* in_sizes, int n_in,
                              void* d_out, int out_size)
{
    (void)in_sizes; (void)n_in; (void)out_size;
    const float* x  = (const float*)d_in[0];
    const float* wq = (const float*)d_in[1];
    const float* bq = (const float*)d_in[2];
    const float* wk = (const float*)d_in[3];
    const float* bk = (const float*)d_in[4];
    const float* wv = (const float*)d_in[5];
    const float* bv = (const float*)d_in[6];
    const float* wo = (const float*)d_in[7];
    const float* bo = (const float*)d_in[8];
    float* out = (float*)d_out;

    wfrag_kernel<<<256, 256>>>(wq, wk, wv, wo);
    qkv_mma_kernel<<<dim3(PTOT / 128, DM / 128, 3), 256>>>(x, bq, bk, bv);
    attn_kernel<<<dim3(14, NB * NH), 128>>>();
    oproj_mma_kernel<<<dim3(PTOT / 128, DM / 128), 256>>>(bo, out);
}